// round 1
// baseline (speedup 1.0000x reference)
#include <cuda_runtime.h>

#define Bdim 2
#define Tdim 2048
#define Edim 1024
#define Hdim 16
#define HD 64
#define QKV3 192
#define KT 32          // keys per tile in attention
#define QTILE 128      // queries per block

// Scratch: Q/K/V in [B, H, T, HD] layout. 16 MB each.
__device__ float g_Q[Bdim * Hdim * Tdim * HD];
__device__ float g_K[Bdim * Hdim * Tdim * HD];
__device__ float g_V[Bdim * Hdim * Tdim * HD];

// ---------------------------------------------------------------------------
// Kernel 1: QKV projection.
// Grid: B*T blocks, 192 threads. Thread d owns output column d for ALL 16
// heads (W column shared across heads -> load W[:,d] once into registers).
// q is pre-scaled by 1/sqrt(HD).
// ---------------------------------------------------------------------------
__global__ __launch_bounds__(QKV3) void qkv_proj_kernel(
    const float* __restrict__ x,      // [B, T, E]
    const float* __restrict__ W,      // [HD, 3*HD]
    const float* __restrict__ bias)   // [3*HD]
{
    __shared__ float xs[Edim];
    const int bt = blockIdx.x;
    const int b  = bt / Tdim;
    const int t  = bt % Tdim;

    const float* xrow = x + (size_t)bt * Edim;
    for (int i = threadIdx.x; i < Edim; i += QKV3) xs[i] = xrow[i];
    __syncthreads();

    const int d = threadIdx.x;  // 0..191

    // Load this thread's W column (stride QKV3 across k; coalesced across d).
    float wreg[HD];
#pragma unroll 8
    for (int k = 0; k < HD; k++) wreg[k] = W[k * QKV3 + d];

    const float bv = bias[d];
    float acc[Hdim];
#pragma unroll
    for (int h = 0; h < Hdim; h++) acc[h] = bv;

    const float4* xs4 = (const float4*)xs;
#pragma unroll
    for (int h = 0; h < Hdim; h++) {
        float a = acc[h];
#pragma unroll
        for (int k4 = 0; k4 < HD / 4; k4++) {
            float4 xv = xs4[h * (HD / 4) + k4];
            a = fmaf(xv.x, wreg[k4 * 4 + 0], a);
            a = fmaf(xv.y, wreg[k4 * 4 + 1], a);
            a = fmaf(xv.z, wreg[k4 * 4 + 2], a);
            a = fmaf(xv.w, wreg[k4 * 4 + 3], a);
        }
        acc[h] = a;
    }

#pragma unroll
    for (int h = 0; h < Hdim; h++) {
        const size_t off = ((size_t)(b * Hdim + h) * Tdim + t) * HD;
        if (d < HD) {
            g_Q[off + d] = acc[h] * 0.125f;   // 1/sqrt(64) folded into Q
        } else if (d < 2 * HD) {
            g_K[off + d - HD] = acc[h];
        } else {
            g_V[off + d - 2 * HD] = acc[h];
        }
    }
}

// ---------------------------------------------------------------------------
// Kernel 2: flash attention.
// Grid: (T/QTILE, B*H), 128 threads. Thread i owns query row (tile*128 + i):
// q[64], o[64] in registers; K/V tiles of KT=32 keys in smem (broadcast reads,
// float4-vectorized so LDS:FMA = 1:4). Online softmax with __expf.
// ---------------------------------------------------------------------------
__global__ __launch_bounds__(QTILE, 1) void attn_kernel(float* __restrict__ out)
{
    __shared__ float4 Ks[KT * (HD / 4)];
    __shared__ float4 Vs[KT * (HD / 4)];

    const int bh = blockIdx.y;
    const int b  = bh >> 4;           // H = 16
    const int h  = bh & 15;
    const int t  = blockIdx.x * QTILE + threadIdx.x;

    const float4* Q4 = (const float4*)(g_Q + ((size_t)bh * Tdim + t) * HD);
    float4 q[HD / 4], o[HD / 4];
#pragma unroll
    for (int i = 0; i < HD / 4; i++) {
        q[i] = Q4[i];
        o[i] = make_float4(0.f, 0.f, 0.f, 0.f);
    }

    float m = -1e30f;
    float l = 0.f;

    const float4* Kbase = (const float4*)(g_K + (size_t)bh * Tdim * HD);
    const float4* Vbase = (const float4*)(g_V + (size_t)bh * Tdim * HD);

    for (int kt = 0; kt < Tdim / KT; kt++) {
        // Cooperative tile load: KT*HD floats = 512 float4 = 4 per thread.
        const float4* Ksrc = Kbase + kt * KT * (HD / 4);
        const float4* Vsrc = Vbase + kt * KT * (HD / 4);
#pragma unroll
        for (int i = 0; i < (KT * HD / 4) / QTILE; i++) {
            Ks[threadIdx.x + i * QTILE] = Ksrc[threadIdx.x + i * QTILE];
            Vs[threadIdx.x + i * QTILE] = Vsrc[threadIdx.x + i * QTILE];
        }
        __syncthreads();

        // Scores for this thread's query row against KT keys.
        float s[KT];
        float tmax = m;
#pragma unroll
        for (int j = 0; j < KT; j++) {
            float acc = 0.f;
#pragma unroll
            for (int d4 = 0; d4 < HD / 4; d4++) {
                float4 kv = Ks[j * (HD / 4) + d4];
                acc = fmaf(q[d4].x, kv.x, acc);
                acc = fmaf(q[d4].y, kv.y, acc);
                acc = fmaf(q[d4].z, kv.z, acc);
                acc = fmaf(q[d4].w, kv.w, acc);
            }
            s[j] = acc;
            tmax = fmaxf(tmax, acc);
        }

        // Online softmax rescale.
        const float corr = __expf(m - tmax);
        m = tmax;
        l *= corr;
#pragma unroll
        for (int i = 0; i < HD / 4; i++) {
            o[i].x *= corr; o[i].y *= corr; o[i].z *= corr; o[i].w *= corr;
        }

        // P·V accumulation.
#pragma unroll
        for (int j = 0; j < KT; j++) {
            const float p = __expf(s[j] - m);
            l += p;
#pragma unroll
            for (int d4 = 0; d4 < HD / 4; d4++) {
                float4 vv = Vs[j * (HD / 4) + d4];
                o[d4].x = fmaf(p, vv.x, o[d4].x);
                o[d4].y = fmaf(p, vv.y, o[d4].y);
                o[d4].z = fmaf(p, vv.z, o[d4].z);
                o[d4].w = fmaf(p, vv.w, o[d4].w);
            }
        }
        __syncthreads();
    }

    // Epilogue: out[b, t, h*HD + d] = o[d] / l
    const float inv = 1.f / l;
    float4* out4 = (float4*)(out + ((size_t)(b * Tdim + t)) * Edim + h * HD);
#pragma unroll
    for (int i = 0; i < HD / 4; i++) {
        float4 v;
        v.x = o[i].x * inv;
        v.y = o[i].y * inv;
        v.z = o[i].z * inv;
        v.w = o[i].w * inv;
        out4[i] = v;
    }
}

// ---------------------------------------------------------------------------
extern "C" void kernel_launch(void* const* d_in, const int* in_sizes, int n_in,
                              void* d_out, int out_size)
{
    const float* x    = (const float*)d_in[0];   // [2, 2048, 1024]
    const float* W    = (const float*)d_in[1];   // [64, 192]
    const float* bias = (const float*)d_in[2];   // [192]
    float* out = (float*)d_out;                  // [2, 2048, 1024]

    qkv_proj_kernel<<<Bdim * Tdim, QKV3>>>(x, W, bias);

    dim3 grid(Tdim / QTILE, Bdim * Hdim);
    attn_kernel<<<grid, QTILE>>>(out);
}

// round 2
// speedup vs baseline: 1.0653x; 1.0653x over previous
#include <cuda_runtime.h>

#define Bdim 2
#define Tdim 2048
#define Edim 1024
#define Hdim 16
#define HD 64
#define QKV3 192
#define KT 32          // keys per tile in attention
#define QTILE 128      // queries per block

// Scratch: Q/K/V in [B, H, T, HD] layout. 16 MB each.
__device__ float g_Q[Bdim * Hdim * Tdim * HD];
__device__ float g_K[Bdim * Hdim * Tdim * HD];
__device__ float g_V[Bdim * Hdim * Tdim * HD];

// ---------------------------------------------------------------------------
// Packed f32x2 helpers (Blackwell FFMA2 — only reachable via PTX).
// A ull holds two floats: lo = first float in memory order, hi = second.
// ---------------------------------------------------------------------------
typedef unsigned long long ull;

__device__ __forceinline__ ull fma2(ull a, ull b, ull c) {
    ull d;
    asm("fma.rn.f32x2 %0, %1, %2, %3;" : "=l"(d) : "l"(a), "l"(b), "l"(c));
    return d;
}
__device__ __forceinline__ ull mul2(ull a, ull b) {
    ull d;
    asm("mul.rn.f32x2 %0, %1, %2;" : "=l"(d) : "l"(a), "l"(b));
    return d;
}
__device__ __forceinline__ ull pack2(float lo, float hi) {
    ull r;
    asm("mov.b64 %0, {%1, %2};" : "=l"(r) : "f"(lo), "f"(hi));
    return r;
}
__device__ __forceinline__ void unpack2(ull v, float& lo, float& hi) {
    asm("mov.b64 {%0, %1}, %2;" : "=f"(lo), "=f"(hi) : "l"(v));
}

// ---------------------------------------------------------------------------
// Kernel 1: QKV projection (f32x2 inner loop).
// Grid: B*T blocks, 192 threads. Thread d owns output column d for ALL 16
// heads. q is pre-scaled by 1/sqrt(HD).
// ---------------------------------------------------------------------------
__global__ __launch_bounds__(QKV3) void qkv_proj_kernel(
    const float* __restrict__ x,      // [B, T, E]
    const float* __restrict__ W,      // [HD, 3*HD]
    const float* __restrict__ bias)   // [3*HD]
{
    __shared__ __align__(16) float xs[Edim];
    const int bt = blockIdx.x;
    const int b  = bt / Tdim;
    const int t  = bt % Tdim;

    const float* xrow = x + (size_t)bt * Edim;
    for (int i = threadIdx.x; i < Edim; i += QKV3) xs[i] = xrow[i];
    __syncthreads();

    const int d = threadIdx.x;  // 0..191

    // W column as 32 packed pairs (pair k2 = (W[2k2][d], W[2k2+1][d])).
    ull w2[HD / 2];
#pragma unroll 8
    for (int k2 = 0; k2 < HD / 2; k2++)
        w2[k2] = pack2(W[(2 * k2) * QKV3 + d], W[(2 * k2 + 1) * QKV3 + d]);

    const float bv = bias[d];
    const ull* xs2 = (const ull*)xs;   // pair i = (xs[2i], xs[2i+1])

    float acc[Hdim];
#pragma unroll
    for (int h = 0; h < Hdim; h++) {
        ull a0 = 0ULL, a1 = 0ULL;      // two chains for ILP
#pragma unroll
        for (int k2 = 0; k2 < HD / 2; k2 += 2) {
            a0 = fma2(xs2[h * (HD / 2) + k2],     w2[k2],     a0);
            a1 = fma2(xs2[h * (HD / 2) + k2 + 1], w2[k2 + 1], a1);
        }
        float l0, h0, l1, h1;
        unpack2(a0, l0, h0);
        unpack2(a1, l1, h1);
        acc[h] = bv + ((l0 + h0) + (l1 + h1));
    }

#pragma unroll
    for (int h = 0; h < Hdim; h++) {
        const size_t off = ((size_t)(b * Hdim + h) * Tdim + t) * HD;
        if (d < HD) {
            g_Q[off + d] = acc[h] * 0.125f;   // 1/sqrt(64) folded into Q
        } else if (d < 2 * HD) {
            g_K[off + d - HD] = acc[h];
        } else {
            g_V[off + d - 2 * HD] = acc[h];
        }
    }
}

// ---------------------------------------------------------------------------
// Kernel 2: flash attention with packed f32x2 math.
// Grid: (T/QTILE, B*H), 128 threads. Thread i owns one query row.
// ---------------------------------------------------------------------------
__global__ __launch_bounds__(QTILE, 1) void attn_kernel(float* __restrict__ out)
{
    __shared__ __align__(16) ulonglong2 Ks[KT * (HD / 4)];
    __shared__ __align__(16) ulonglong2 Vs[KT * (HD / 4)];

    const int bh = blockIdx.y;
    const int b  = bh >> 4;           // H = 16
    const int h  = bh & 15;
    const int t  = blockIdx.x * QTILE + threadIdx.x;

    // q, o as 32 packed f32x2 values each.
    const ulonglong2* Q4 = (const ulonglong2*)(g_Q + ((size_t)bh * Tdim + t) * HD);
    ull q2[HD / 2], o2[HD / 2];
#pragma unroll
    for (int i = 0; i < HD / 4; i++) {
        ulonglong2 v = Q4[i];
        q2[2 * i]     = v.x;
        q2[2 * i + 1] = v.y;
        o2[2 * i]     = 0ULL;
        o2[2 * i + 1] = 0ULL;
    }

    float m = -1e30f;
    float l0 = 0.f, l1 = 0.f;

    const ulonglong2* Kbase = (const ulonglong2*)(g_K + (size_t)bh * Tdim * HD);
    const ulonglong2* Vbase = (const ulonglong2*)(g_V + (size_t)bh * Tdim * HD);

    for (int kt = 0; kt < Tdim / KT; kt++) {
        // Cooperative tile load: 512 16B vectors, 4 per thread per array.
        const ulonglong2* Ksrc = Kbase + kt * KT * (HD / 4);
        const ulonglong2* Vsrc = Vbase + kt * KT * (HD / 4);
#pragma unroll
        for (int i = 0; i < (KT * HD / 4) / QTILE; i++) {
            Ks[threadIdx.x + i * QTILE] = Ksrc[threadIdx.x + i * QTILE];
            Vs[threadIdx.x + i * QTILE] = Vsrc[threadIdx.x + i * QTILE];
        }
        __syncthreads();

        // Scores: packed dot product, two accumulator chains.
        float s[KT];
        float tmax = m;
#pragma unroll
        for (int j = 0; j < KT; j++) {
            ull a0 = 0ULL, a1 = 0ULL;
#pragma unroll
            for (int d4 = 0; d4 < HD / 4; d4++) {
                ulonglong2 kv = Ks[j * (HD / 4) + d4];
                a0 = fma2(q2[2 * d4],     kv.x, a0);
                a1 = fma2(q2[2 * d4 + 1], kv.y, a1);
            }
            float x0, x1, y0, y1;
            unpack2(a0, x0, x1);
            unpack2(a1, y0, y1);
            const float sc = (x0 + x1) + (y0 + y1);
            s[j] = sc;
            tmax = fmaxf(tmax, sc);
        }

        // Online softmax rescale.
        const float corr = __expf(m - tmax);
        m = tmax;
        l0 *= corr;
        l1 *= corr;
        const ull cc = pack2(corr, corr);
#pragma unroll
        for (int i = 0; i < HD / 2; i++) o2[i] = mul2(o2[i], cc);

        // P·V accumulation (packed).
#pragma unroll
        for (int j = 0; j < KT; j++) {
            const float p = __expf(s[j] - m);
            if (j & 1) l1 += p; else l0 += p;
            const ull pp = pack2(p, p);
#pragma unroll
            for (int d4 = 0; d4 < HD / 4; d4++) {
                ulonglong2 vv = Vs[j * (HD / 4) + d4];
                o2[2 * d4]     = fma2(pp, vv.x, o2[2 * d4]);
                o2[2 * d4 + 1] = fma2(pp, vv.y, o2[2 * d4 + 1]);
            }
        }
        __syncthreads();
    }

    // Epilogue: out[b, t, h*HD + d] = o[d] / l
    const float inv = 1.f / (l0 + l1);
    float* op = out + ((size_t)(b * Tdim + t)) * Edim + h * HD;
#pragma unroll
    for (int i = 0; i < HD / 2; i++) {
        float lo, hi;
        unpack2(o2[i], lo, hi);
        op[2 * i]     = lo * inv;
        op[2 * i + 1] = hi * inv;
    }
}

// ---------------------------------------------------------------------------
extern "C" void kernel_launch(void* const* d_in, const int* in_sizes, int n_in,
                              void* d_out, int out_size)
{
    const float* x    = (const float*)d_in[0];   // [2, 2048, 1024]
    const float* W    = (const float*)d_in[1];   // [64, 192]
    const float* bias = (const float*)d_in[2];   // [192]
    float* out = (float*)d_out;                  // [2, 2048, 1024]

    qkv_proj_kernel<<<Bdim * Tdim, QKV3>>>(x, W, bias);

    dim3 grid(Tdim / QTILE, Bdim * Hdim);
    attn_kernel<<<grid, QTILE>>>(out);
}

// round 4
// speedup vs baseline: 1.0787x; 1.0126x over previous
#include <cuda_runtime.h>

#define Bdim 2
#define Tdim 2048
#define Edim 1024
#define Hdim 16
#define HD 64
#define QKV3 192
#define KT 16          // keys per tile in attention
#define QTILE 128      // queries per block
#define NT (Tdim / KT) // 128 tiles

// Scratch: Q/K/V in [B, H, T, HD] layout. 16 MB each.
__device__ float g_Q[Bdim * Hdim * Tdim * HD];
__device__ float g_K[Bdim * Hdim * Tdim * HD];
__device__ float g_V[Bdim * Hdim * Tdim * HD];

// ---------------------------------------------------------------------------
// Packed f32x2 helpers (Blackwell FFMA2 — only reachable via PTX).
// ---------------------------------------------------------------------------
typedef unsigned long long ull;

__device__ __forceinline__ ull fma2(ull a, ull b, ull c) {
    ull d;
    asm("fma.rn.f32x2 %0, %1, %2, %3;" : "=l"(d) : "l"(a), "l"(b), "l"(c));
    return d;
}
__device__ __forceinline__ ull mul2(ull a, ull b) {
    ull d;
    asm("mul.rn.f32x2 %0, %1, %2;" : "=l"(d) : "l"(a), "l"(b));
    return d;
}
__device__ __forceinline__ ull pack2(float lo, float hi) {
    ull r;
    asm("mov.b64 %0, {%1, %2};" : "=l"(r) : "f"(lo), "f"(hi));
    return r;
}
__device__ __forceinline__ void unpack2(ull v, float& lo, float& hi) {
    asm("mov.b64 {%0, %1}, %2;" : "=f"(lo), "=f"(hi) : "l"(v));
}

// ---------------------------------------------------------------------------
// Kernel 1: QKV projection (f32x2 inner loop). Unchanged (verified R2).
// ---------------------------------------------------------------------------
__global__ __launch_bounds__(QKV3) void qkv_proj_kernel(
    const float* __restrict__ x,      // [B, T, E]
    const float* __restrict__ W,      // [HD, 3*HD]
    const float* __restrict__ bias)   // [3*HD]
{
    __shared__ __align__(16) float xs[Edim];
    const int bt = blockIdx.x;
    const int b  = bt / Tdim;
    const int t  = bt % Tdim;

    const float* xrow = x + (size_t)bt * Edim;
    for (int i = threadIdx.x; i < Edim; i += QKV3) xs[i] = xrow[i];
    __syncthreads();

    const int d = threadIdx.x;  // 0..191

    ull w2[HD / 2];
#pragma unroll 8
    for (int k2 = 0; k2 < HD / 2; k2++)
        w2[k2] = pack2(W[(2 * k2) * QKV3 + d], W[(2 * k2 + 1) * QKV3 + d]);

    const float bv = bias[d];
    const ull* xs2 = (const ull*)xs;

    float acc[Hdim];
#pragma unroll
    for (int h = 0; h < Hdim; h++) {
        ull a0 = 0ULL, a1 = 0ULL;
#pragma unroll
        for (int k2 = 0; k2 < HD / 2; k2 += 2) {
            a0 = fma2(xs2[h * (HD / 2) + k2],     w2[k2],     a0);
            a1 = fma2(xs2[h * (HD / 2) + k2 + 1], w2[k2 + 1], a1);
        }
        float l0, h0, l1, h1;
        unpack2(a0, l0, h0);
        unpack2(a1, l1, h1);
        acc[h] = bv + ((l0 + h0) + (l1 + h1));
    }

#pragma unroll
    for (int h = 0; h < Hdim; h++) {
        const size_t off = ((size_t)(b * Hdim + h) * Tdim + t) * HD;
        if (d < HD) {
            g_Q[off + d] = acc[h] * 0.125f;   // 1/sqrt(64) folded into Q
        } else if (d < 2 * HD) {
            g_K[off + d - HD] = acc[h];
        } else {
            g_V[off + d - 2 * HD] = acc[h];
        }
    }
}

// ---------------------------------------------------------------------------
// Kernel 2: flash attention, f32x2 math, double-buffered smem + reg prefetch.
// Grid: (T/QTILE, B*H), 128 threads. Thread i owns one query row.
// A key row = HD floats = 16 ulonglong2. A tile = KT*16 = 256 ulonglong2.
// ---------------------------------------------------------------------------
#define ROW_V2  (HD / 4)              // ulonglong2 per key row = 16
#define TILE_V2 (KT * ROW_V2)         // ulonglong2 per tile per array = 256
#define LD_PER_THR (TILE_V2 / QTILE)  // vectors per thread per array = 2

__global__ __launch_bounds__(QTILE, 1) void attn_kernel(float* __restrict__ out)
{
    // Double-buffered K/V tiles: 2 arrays * 2 bufs * 256 * 16B = 16 KB
    __shared__ __align__(16) ulonglong2 Ks[2][TILE_V2];
    __shared__ __align__(16) ulonglong2 Vs[2][TILE_V2];

    const int bh = blockIdx.y;
    const int b  = bh >> 4;           // H = 16
    const int h  = bh & 15;
    const int t  = blockIdx.x * QTILE + threadIdx.x;

    const ulonglong2* Q4 = (const ulonglong2*)(g_Q + ((size_t)bh * Tdim + t) * HD);
    ull q2[HD / 2], o2[HD / 2];
#pragma unroll
    for (int i = 0; i < HD / 4; i++) {
        ulonglong2 v = Q4[i];
        q2[2 * i]     = v.x;
        q2[2 * i + 1] = v.y;
        o2[2 * i]     = 0ULL;
        o2[2 * i + 1] = 0ULL;
    }

    float m = -1e30f;
    float l0 = 0.f, l1 = 0.f;

    const ulonglong2* Kbase = (const ulonglong2*)(g_K + (size_t)bh * Tdim * HD);
    const ulonglong2* Vbase = (const ulonglong2*)(g_V + (size_t)bh * Tdim * HD);

    const int i0 = threadIdx.x;          // first vec this thread moves
    const int i1 = threadIdx.x + QTILE;  // second vec

    // Prologue: load tile 0 into buffer 0.
    Ks[0][i0] = Kbase[i0];
    Ks[0][i1] = Kbase[i1];
    Vs[0][i0] = Vbase[i0];
    Vs[0][i1] = Vbase[i1];
    __syncthreads();

    for (int kt = 0; kt < NT; kt++) {
        const int cur = kt & 1;
        const int nxt = cur ^ 1;

        // Prefetch next tile into registers (LDG latency hidden by compute).
        ulonglong2 rK0, rK1, rV0, rV1;
        if (kt + 1 < NT) {
            const ulonglong2* Kn = Kbase + (kt + 1) * TILE_V2;
            const ulonglong2* Vn = Vbase + (kt + 1) * TILE_V2;
            rK0 = Kn[i0]; rK1 = Kn[i1];
            rV0 = Vn[i0]; rV1 = Vn[i1];
        }

        // ---- Scores: 4 independent FFMA2 chains per key. ----
        float s[KT];
        float tmax = m;
#pragma unroll
        for (int j = 0; j < KT; j++) {
            const ulonglong2* krow = &Ks[cur][j * ROW_V2];
            ull a0 = 0ULL, a1 = 0ULL, a2 = 0ULL, a3 = 0ULL;
#pragma unroll
            for (int d8 = 0; d8 < HD / 8; d8++) {   // 8 iters, 2 vecs each
                ulonglong2 kva = krow[2 * d8];
                ulonglong2 kvb = krow[2 * d8 + 1];
                a0 = fma2(q2[4 * d8 + 0], kva.x, a0);
                a1 = fma2(q2[4 * d8 + 1], kva.y, a1);
                a2 = fma2(q2[4 * d8 + 2], kvb.x, a2);
                a3 = fma2(q2[4 * d8 + 3], kvb.y, a3);
            }
            float x0, x1, y0, y1, z0, z1, w0, w1;
            unpack2(a0, x0, x1);
            unpack2(a1, y0, y1);
            unpack2(a2, z0, z1);
            unpack2(a3, w0, w1);
            const float sc = ((x0 + x1) + (y0 + y1)) + ((z0 + z1) + (w0 + w1));
            s[j] = sc;
            tmax = fmaxf(tmax, sc);
        }

        // ---- Online softmax: batch the exps (MUFU, off the FMA pipe). ----
        const float corr = __expf(m - tmax);
        m = tmax;
        float p[KT];
#pragma unroll
        for (int j = 0; j < KT; j++) p[j] = __expf(s[j] - m);

        l0 = l0 * corr;
        l1 = l1 * corr;
#pragma unroll
        for (int j = 0; j < KT; j += 2) { l0 += p[j]; l1 += p[j + 1]; }

        const ull cc = pack2(corr, corr);
#pragma unroll
        for (int i = 0; i < HD / 2; i++) o2[i] = mul2(o2[i], cc);

        // ---- P.V accumulation: 32 independent accumulator chains. ----
#pragma unroll
        for (int j = 0; j < KT; j++) {
            const ull pp = pack2(p[j], p[j]);
            const ulonglong2* vrow = &Vs[cur][j * ROW_V2];
#pragma unroll
            for (int d4 = 0; d4 < ROW_V2; d4++) {
                ulonglong2 vv = vrow[d4];
                o2[2 * d4]     = fma2(pp, vv.x, o2[2 * d4]);
                o2[2 * d4 + 1] = fma2(pp, vv.y, o2[2 * d4 + 1]);
            }
        }

        // ---- Stage prefetched tile into the other buffer. ----
        if (kt + 1 < NT) {
            Ks[nxt][i0] = rK0;
            Ks[nxt][i1] = rK1;
            Vs[nxt][i0] = rV0;
            Vs[nxt][i1] = rV1;
        }
        __syncthreads();
    }

    // Epilogue: out[b, t, h*HD + d] = o[d] / l
    const float inv = 1.f / (l0 + l1);
    float* op = out + ((size_t)(b * Tdim + t)) * Edim + h * HD;
#pragma unroll
    for (int i = 0; i < HD / 2; i++) {
        float lo, hi;
        unpack2(o2[i], lo, hi);
        op[2 * i]     = lo * inv;
        op[2 * i + 1] = hi * inv;
    }
}

// ---------------------------------------------------------------------------
extern "C" void kernel_launch(void* const* d_in, const int* in_sizes, int n_in,
                              void* d_out, int out_size)
{
    const float* x    = (const float*)d_in[0];   // [2, 2048, 1024]
    const float* W    = (const float*)d_in[1];   // [64, 192]
    const float* bias = (const float*)d_in[2];   // [192]
    float* out = (float*)d_out;                  // [2, 2048, 1024]

    qkv_proj_kernel<<<Bdim * Tdim, QKV3>>>(x, W, bias);

    dim3 grid(Tdim / QTILE, Bdim * Hdim);
    attn_kernel<<<grid, QTILE>>>(out);
}

// round 6
// speedup vs baseline: 1.3158x; 1.2198x over previous
#include <cuda_runtime.h>

#define Bdim 2
#define Tdim 2048
#define Edim 1024
#define Hdim 16
#define HD 64
#define QKV3 192
#define KT 16            // keys per tile
#define QTILE 128        // queries per block (2 per thread, 64 pairs)
#define THREADS 128
#define NT (Tdim / KT)   // 128 tiles

// Scratch: Q/K/V in [B, H, T, HD] layout. 16 MB each.
__device__ float g_Q[Bdim * Hdim * Tdim * HD];
__device__ float g_K[Bdim * Hdim * Tdim * HD];
__device__ float g_V[Bdim * Hdim * Tdim * HD];

// ---------------------------------------------------------------------------
// Packed f32x2 helpers (Blackwell FFMA2 — only reachable via PTX).
// ---------------------------------------------------------------------------
typedef unsigned long long ull;

__device__ __forceinline__ ull fma2(ull a, ull b, ull c) {
    ull d;
    asm("fma.rn.f32x2 %0, %1, %2, %3;" : "=l"(d) : "l"(a), "l"(b), "l"(c));
    return d;
}
__device__ __forceinline__ ull mul2(ull a, ull b) {
    ull d;
    asm("mul.rn.f32x2 %0, %1, %2;" : "=l"(d) : "l"(a), "l"(b));
    return d;
}
__device__ __forceinline__ ull pack2(float lo, float hi) {
    ull r;
    asm("mov.b64 %0, {%1, %2};" : "=l"(r) : "f"(lo), "f"(hi));
    return r;
}
__device__ __forceinline__ void unpack2(ull v, float& lo, float& hi) {
    asm("mov.b64 {%0, %1}, %2;" : "=f"(lo), "=f"(hi) : "l"(v));
}

// ---------------------------------------------------------------------------
// Kernel 1: QKV projection (f32x2 inner loop). Unchanged (verified R2).
// ---------------------------------------------------------------------------
__global__ __launch_bounds__(QKV3) void qkv_proj_kernel(
    const float* __restrict__ x,      // [B, T, E]
    const float* __restrict__ W,      // [HD, 3*HD]
    const float* __restrict__ bias)   // [3*HD]
{
    __shared__ __align__(16) float xs[Edim];
    const int bt = blockIdx.x;
    const int b  = bt / Tdim;
    const int t  = bt % Tdim;

    const float* xrow = x + (size_t)bt * Edim;
    for (int i = threadIdx.x; i < Edim; i += QKV3) xs[i] = xrow[i];
    __syncthreads();

    const int d = threadIdx.x;  // 0..191

    ull w2[HD / 2];
#pragma unroll 8
    for (int k2 = 0; k2 < HD / 2; k2++)
        w2[k2] = pack2(W[(2 * k2) * QKV3 + d], W[(2 * k2 + 1) * QKV3 + d]);

    const float bv = bias[d];
    const ull* xs2 = (const ull*)xs;

    float acc[Hdim];
#pragma unroll
    for (int h = 0; h < Hdim; h++) {
        ull a0 = 0ULL, a1 = 0ULL;
#pragma unroll
        for (int k2 = 0; k2 < HD / 2; k2 += 2) {
            a0 = fma2(xs2[h * (HD / 2) + k2],     w2[k2],     a0);
            a1 = fma2(xs2[h * (HD / 2) + k2 + 1], w2[k2 + 1], a1);
        }
        float l0, h0, l1, h1;
        unpack2(a0, l0, h0);
        unpack2(a1, l1, h1);
        acc[h] = bv + ((l0 + h0) + (l1 + h1));
    }

#pragma unroll
    for (int h = 0; h < Hdim; h++) {
        const size_t off = ((size_t)(b * Hdim + h) * Tdim + t) * HD;
        if (d < HD) {
            g_Q[off + d] = acc[h] * 0.125f;   // 1/sqrt(64) folded into Q
        } else if (d < 2 * HD) {
            g_K[off + d - HD] = acc[h];
        } else {
            g_V[off + d - 2 * HD] = acc[h];
        }
    }
}

// ---------------------------------------------------------------------------
// Kernel 2: flash attention, thread-paired: lanes (2i, 2i+1) cooperate on
// 2 query rows, interleaved 16B head-dim ownership. Each K/V smem vector is
// read once and used for both queries -> 4x fewer LDS per query.
// ---------------------------------------------------------------------------
#define ROW_V2  (HD / 4)              // ulonglong2 per key row = 16
#define TILE_V2 (KT * ROW_V2)         // ulonglong2 per tile per array = 256

__global__ __launch_bounds__(THREADS, 1) void attn_kernel(float* __restrict__ out)
{
    // Double-buffered K/V tiles: 2 arrays * 2 bufs * 256 * 16B = 16 KB
    __shared__ __align__(16) ulonglong2 Ks[2][TILE_V2];
    __shared__ __align__(16) ulonglong2 Vs[2][TILE_V2];

    const int bh   = blockIdx.y;
    const int b    = bh >> 4;         // H = 16
    const int h    = bh & 15;
    const int pi   = threadIdx.x >> 1;   // pair index 0..63
    const int half = threadIdx.x & 1;    // which half of dims this lane owns

    const int qa = blockIdx.x * QTILE + 2 * pi;  // even-lane-owned query
    // odd lane owns query qa+1. This lane's owned query = qa + half.

    // q and o for BOTH queries, restricted to owned vecs (2u+half), u=0..7.
    ull qq[2][16], oo[2][16];
#pragma unroll
    for (int x = 0; x < 2; x++) {
        const ulonglong2* Qrow =
            (const ulonglong2*)(g_Q + ((size_t)bh * Tdim + qa + x) * HD);
#pragma unroll
        for (int u = 0; u < 8; u++) {
            ulonglong2 v = Qrow[2 * u + half];
            qq[x][2 * u]     = v.x;
            qq[x][2 * u + 1] = v.y;
            oo[x][2 * u]     = 0ULL;
            oo[x][2 * u + 1] = 0ULL;
        }
    }

    float m  = -1e30f;        // online-softmax state for the OWNED query
    float l0 = 0.f, l1 = 0.f;

    const ulonglong2* Kbase = (const ulonglong2*)(g_K + (size_t)bh * Tdim * HD);
    const ulonglong2* Vbase = (const ulonglong2*)(g_V + (size_t)bh * Tdim * HD);

    const int i0 = threadIdx.x;            // tile-load vec indices
    const int i1 = threadIdx.x + THREADS;

    // Prologue: tile 0 into buffer 0.
    Ks[0][i0] = Kbase[i0];
    Ks[0][i1] = Kbase[i1];
    Vs[0][i0] = Vbase[i0];
    Vs[0][i1] = Vbase[i1];
    __syncthreads();

    for (int kt = 0; kt < NT; kt++) {
        const int cur = kt & 1;
        const int nxt = cur ^ 1;

        // Prefetch next tile into registers.
        ulonglong2 rK0, rK1, rV0, rV1;
        if (kt + 1 < NT) {
            const ulonglong2* Kn = Kbase + (kt + 1) * TILE_V2;
            const ulonglong2* Vn = Vbase + (kt + 1) * TILE_V2;
            rK0 = Kn[i0]; rK1 = Kn[i1];
            rV0 = Vn[i0]; rV1 = Vn[i1];
        }

        // ---- Scores: half-dim partial dots for both queries, then one
        //      shfl_xor(1) per key to combine halves. ----
        float s[KT];
        float tmax = m;
#pragma unroll
        for (int j = 0; j < KT; j++) {
            const ulonglong2* krow = &Ks[cur][j * ROW_V2];
            ull a0 = 0ULL, a1 = 0ULL;   // query qa chains
            ull b0 = 0ULL, b1 = 0ULL;   // query qa+1 chains
#pragma unroll
            for (int u = 0; u < 8; u++) {
                ulonglong2 kv = krow[2 * u + half];
                a0 = fma2(qq[0][2 * u],     kv.x, a0);
                a1 = fma2(qq[0][2 * u + 1], kv.y, a1);
                b0 = fma2(qq[1][2 * u],     kv.x, b0);
                b1 = fma2(qq[1][2 * u + 1], kv.y, b1);
            }
            float ax, ay, az, aw, bx, by, bz, bw;
            unpack2(a0, ax, ay);
            unpack2(a1, az, aw);
            unpack2(b0, bx, by);
            unpack2(b1, bz, bw);
            const float pa = (ax + ay) + (az + aw);  // partial, query qa
            const float pb = (bx + by) + (bz + bw);  // partial, query qa+1
            const float p_own = half ? pb : pa;
            const float p_oth = half ? pa : pb;
            const float recv = __shfl_xor_sync(0xffffffffu, p_oth, 1);
            const float sc = p_own + recv;
            s[j] = sc;
            tmax = fmaxf(tmax, sc);
        }

        // ---- Online softmax for the owned query. ----
        const float corr = __expf(m - tmax);
        m = tmax;
        float p[KT];
#pragma unroll
        for (int j = 0; j < KT; j++) p[j] = __expf(s[j] - m);

        l0 = l0 * corr;
        l1 = l1 * corr;
#pragma unroll
        for (int j = 0; j < KT; j += 2) { l0 += p[j]; l1 += p[j + 1]; }

        // Rescale both o accumulators with per-query corr.
        const float corr_oth = __shfl_xor_sync(0xffffffffu, corr, 1);
        const float corr_a = half ? corr_oth : corr;
        const float corr_b = half ? corr : corr_oth;
        const ull ca = pack2(corr_a, corr_a);
        const ull cb = pack2(corr_b, corr_b);
#pragma unroll
        for (int i = 0; i < 16; i++) {
            oo[0][i] = mul2(oo[0][i], ca);
            oo[1][i] = mul2(oo[1][i], cb);
        }

        // ---- P.V: one V read per thread serves both queries. ----
#pragma unroll
        for (int j = 0; j < KT; j++) {
            const float p_oth = __shfl_xor_sync(0xffffffffu, p[j], 1);
            const float pa_f = half ? p_oth : p[j];
            const float pb_f = half ? p[j] : p_oth;
            const ull pa = pack2(pa_f, pa_f);
            const ull pb = pack2(pb_f, pb_f);
            const ulonglong2* vrow = &Vs[cur][j * ROW_V2];
#pragma unroll
            for (int u = 0; u < 8; u++) {
                ulonglong2 vv = vrow[2 * u + half];
                oo[0][2 * u]     = fma2(pa, vv.x, oo[0][2 * u]);
                oo[0][2 * u + 1] = fma2(pa, vv.y, oo[0][2 * u + 1]);
                oo[1][2 * u]     = fma2(pb, vv.x, oo[1][2 * u]);
                oo[1][2 * u + 1] = fma2(pb, vv.y, oo[1][2 * u + 1]);
            }
        }

        // ---- Stage prefetched tile into the other buffer. ----
        if (kt + 1 < NT) {
            Ks[nxt][i0] = rK0;
            Ks[nxt][i1] = rK1;
            Vs[nxt][i0] = rV0;
            Vs[nxt][i1] = rV1;
        }
        __syncthreads();
    }

    // ---- Epilogue: exchange l, normalize, write owned vecs of both rows. ----
    const float l_own = l0 + l1;
    const float l_oth = __shfl_xor_sync(0xffffffffu, l_own, 1);
    const float inva_f = 1.f / (half ? l_oth : l_own);
    const float invb_f = 1.f / (half ? l_own : l_oth);
    const ull inva = pack2(inva_f, inva_f);
    const ull invb = pack2(invb_f, invb_f);

#pragma unroll
    for (int x = 0; x < 2; x++) {
        ulonglong2* orow =
            (ulonglong2*)(out + ((size_t)(b * Tdim + qa + x)) * Edim + h * HD);
        const ull inv = x ? invb : inva;
#pragma unroll
        for (int u = 0; u < 8; u++) {
            ulonglong2 v;
            v.x = mul2(oo[x][2 * u],     inv);
            v.y = mul2(oo[x][2 * u + 1], inv);
            orow[2 * u + half] = v;
        }
    }
}

// ---------------------------------------------------------------------------
extern "C" void kernel_launch(void* const* d_in, const int* in_sizes, int n_in,
                              void* d_out, int out_size)
{
    const float* x    = (const float*)d_in[0];   // [2, 2048, 1024]
    const float* W    = (const float*)d_in[1];   // [64, 192]
    const float* bias = (const float*)d_in[2];   // [192]
    float* out = (float*)d_out;                  // [2, 2048, 1024]

    qkv_proj_kernel<<<Bdim * Tdim, QKV3>>>(x, W, bias);

    dim3 grid(Tdim / QTILE, Bdim * Hdim);   // 16 x 32 = 512 blocks
    attn_kernel<<<grid, THREADS>>>(out);
}